// round 2
// baseline (speedup 1.0000x reference)
#include <cuda_runtime.h>
#include <cuda_bf16.h>
#include <math.h>

// ---------------- problem constants ----------------
#define Bc   2
#define Tc   1024
#define Vc   32000
#define Dc   1024
#define Hc   16
#define Lc   4
#define DHc  64
#define DFFc 2730
#define NTc  (Bc*Tc)          // 2048 tokens
#define EPSf 1e-6f

// ---------------- scratch (static device globals; no allocs) ----------------
__device__ float g_x  [NTc*Dc];            // residual stream
__device__ float g_xn [NTc*Dc];            // normalized
__device__ float g_qkv[NTc*3*Dc];          // qkv projection
__device__ float g_q  [Bc*Hc*Tc*DHc];     // [b,h,t,d]
__device__ float g_k  [Bc*Hc*Tc*DHc];     // [b,h,t,d]
__device__ float g_vt [Bc*Hc*DHc*Tc];     // [b,h,d,t]  (transposed V)
__device__ float g_s4 [(size_t)Bc*Hc*Tc*Tc]; // scores after sigmoid^4 (128MB)
__device__ float g_rs [Bc*Hc*Tc];          // row sums of s4
__device__ float g_o  [Bc*Hc*Tc*DHc];     // attn out per head
__device__ float g_om [NTc*Dc];            // merged heads / ff output reuse
__device__ float g_tmp[NTc*2*DFFc];        // merged FF (also attn out-proj dest)
__device__ float g_hid[NTc*DFFc];          // swiglu hidden

__device__ __forceinline__ float rsig(float x) {
    return 0.5f * (x / (fabsf(x) + 1.0f) + 1.0f);
}

// ---------------- GEMM: C[M,N] = A[M,K] @ W[N,K]^T  (batched via blockIdx.z) ----------------
#define TM 64
#define TN 64
#define TK 16
enum { EPI_NONE = 0, EPI_SCORES = 1, EPI_DIV = 2 };

template<int EPI>
__global__ void __launch_bounds__(256)
gemm_tn(const float* __restrict__ A, const float* __restrict__ W, float* __restrict__ C,
        int M, int N, int K,
        long long sA, long long sW, long long sC,
        const float* __restrict__ rdiv)
{
    __shared__ float As[TK][TM + 2];
    __shared__ float Ws[TK][TN + 2];

    const int bz = blockIdx.z;
    A += (long long)bz * sA;
    W += (long long)bz * sW;
    C += (long long)bz * sC;

    const int m0 = blockIdx.y * TM;
    const int n0 = blockIdx.x * TN;
    const int tx = threadIdx.x, ty = threadIdx.y;
    const int tid = ty * 16 + tx;

    float acc[4][4] = {};

    for (int k0 = 0; k0 < K; k0 += TK) {
        #pragma unroll
        for (int i = 0; i < 4; i++) {
            int e  = i * 256 + tid;
            int kk = e & 15;
            int r  = e >> 4;
            int gk = k0 + kk;
            int gm = m0 + r;
            As[kk][r] = (gm < M && gk < K) ? A[(long long)gm * K + gk] : 0.0f;
            int gn = n0 + r;
            Ws[kk][r] = (gn < N && gk < K) ? W[(long long)gn * K + gk] : 0.0f;
        }
        __syncthreads();

        #pragma unroll
        for (int kk = 0; kk < TK; kk++) {
            float a[4], b[4];
            #pragma unroll
            for (int i = 0; i < 4; i++) a[i] = As[kk][ty + i * 16];
            #pragma unroll
            for (int j = 0; j < 4; j++) b[j] = Ws[kk][tx + j * 16];
            #pragma unroll
            for (int i = 0; i < 4; i++)
                #pragma unroll
                for (int j = 0; j < 4; j++)
                    acc[i][j] = fmaf(a[i], b[j], acc[i][j]);
        }
        __syncthreads();
    }

    #pragma unroll
    for (int i = 0; i < 4; i++) {
        int gm = m0 + ty + i * 16;
        if (gm >= M) continue;
        #pragma unroll
        for (int j = 0; j < 4; j++) {
            int gn = n0 + tx + j * 16;
            if (gn >= N) continue;
            float v = acc[i][j];
            if (EPI == EPI_SCORES) {
                int   h     = bz & (Hc - 1);
                float slope = exp2f(-0.5f * (float)(h + 1));
                v = v * 0.125f - slope * fabsf((float)(gm - gn));
                if (gm < gn) v = -10000.0f;
                float p = rsig(v);
                p = p * p;
                v = p * p;                       // sigmoid^4
            } else if (EPI == EPI_DIV) {
                v = v / (rdiv[(long long)bz * M + gm] + EPSf);
            }
            C[(long long)gm * N + gn] = v;
        }
    }
}

// ---------------- elementwise / reduction kernels ----------------

__global__ void embed_kernel(const int* __restrict__ ids, const float* __restrict__ emb)
{
    long long idx = (long long)blockIdx.x * blockDim.x + threadIdx.x;
    if (idx >= (long long)NTc * Dc) return;
    int tok = (int)(idx / Dc);
    int d   = (int)(idx % Dc);
    g_x[idx] = emb[(long long)ids[tok] * Dc + d];
}

// mean-error norm: o = x / (mean|x| + eps) * w   -- one block per row
__global__ void __launch_bounds__(256)
norm_kernel(const float* __restrict__ x, const float* __restrict__ w, float* __restrict__ o)
{
    int row = blockIdx.x;
    const float* xr = x + (long long)row * Dc;
    float s = 0.0f;
    for (int d = threadIdx.x; d < Dc; d += 256) s += fabsf(xr[d]);
    // reduce
    #pragma unroll
    for (int off = 16; off > 0; off >>= 1) s += __shfl_xor_sync(0xffffffffu, s, off);
    __shared__ float red[8];
    int wid = threadIdx.x >> 5, lid = threadIdx.x & 31;
    if (lid == 0) red[wid] = s;
    __syncthreads();
    __shared__ float s_inv;
    if (threadIdx.x == 0) {
        float t = 0.0f;
        #pragma unroll
        for (int i = 0; i < 8; i++) t += red[i];
        s_inv = 1.0f / (t * (1.0f / Dc) + EPSf);
    }
    __syncthreads();
    float inv = s_inv;
    float* orow = o + (long long)row * Dc;
    for (int d = threadIdx.x; d < Dc; d += 256) orow[d] = xr[d] * inv * w[d];
}

__global__ void split_qkv_kernel()
{
    long long idx = (long long)blockIdx.x * blockDim.x + threadIdx.x;
    if (idx >= (long long)NTc * 3 * Dc) return;
    int tok = (int)(idx / (3 * Dc));
    int r   = (int)(idx % (3 * Dc));
    int c   = r / Dc;
    int hd  = r % Dc;
    int h   = hd / DHc;
    int d   = hd % DHc;
    int b   = tok / Tc;
    int t   = tok % Tc;
    float v = g_qkv[idx];
    long long bh = (long long)(b * Hc + h);
    if      (c == 0) g_q [(bh * Tc + t) * DHc + d] = v;
    else if (c == 1) g_k [(bh * Tc + t) * DHc + d] = v;
    else             g_vt[(bh * DHc + d) * Tc + t] = v;
}

// sum of s4 over key dim -- one block per (b,h,t) row
__global__ void __launch_bounds__(256)
rowsum_kernel()
{
    int row = blockIdx.x;                  // 0 .. B*H*T-1
    const float* sr = g_s4 + (long long)row * Tc;
    float s = 0.0f;
    for (int j = threadIdx.x; j < Tc; j += 256) s += sr[j];
    #pragma unroll
    for (int off = 16; off > 0; off >>= 1) s += __shfl_xor_sync(0xffffffffu, s, off);
    __shared__ float red[8];
    int wid = threadIdx.x >> 5, lid = threadIdx.x & 31;
    if (lid == 0) red[wid] = s;
    __syncthreads();
    if (threadIdx.x == 0) {
        float t = 0.0f;
        #pragma unroll
        for (int i = 0; i < 8; i++) t += red[i];
        g_rs[row] = t;
    }
}

__global__ void merge_heads_kernel()
{
    long long idx = (long long)blockIdx.x * blockDim.x + threadIdx.x;
    if (idx >= (long long)Bc * Hc * Tc * DHc) return;
    int d = (int)(idx % DHc);
    int t = (int)((idx / DHc) % Tc);
    int h = (int)((idx / ((long long)DHc * Tc)) % Hc);
    int b = (int)(idx / ((long long)DHc * Tc * Hc));
    g_om[((long long)(b * Tc + t)) * Dc + h * DHc + d] = g_o[idx];
}

__global__ void add_kernel(const float* __restrict__ y, long long n)
{
    long long idx = (long long)blockIdx.x * blockDim.x + threadIdx.x;
    if (idx < n) g_x[idx] += y[idx];
}

__global__ void swiglu_kernel()
{
    long long idx = (long long)blockIdx.x * blockDim.x + threadIdx.x;
    if (idx >= (long long)NTc * DFFc) return;
    int tok = (int)(idx / DFFc);
    int j   = (int)(idx % DFFc);
    float g = g_tmp[(long long)tok * 2 * DFFc + j];
    float v = g_tmp[(long long)tok * 2 * DFFc + DFFc + j];
    g_hid[idx] = g * rsig(g) * v;
}

// ---------------- host side ----------------

static inline void gemm_launch(int epi,
                               const float* A, const float* W, float* C,
                               int M, int N, int K,
                               long long sA, long long sW, long long sC,
                               int batch, const float* rdiv)
{
    dim3 grid((N + TN - 1) / TN, (M + TM - 1) / TM, batch);
    dim3 block(16, 16);
    if (epi == EPI_NONE)
        gemm_tn<EPI_NONE><<<grid, block>>>(A, W, C, M, N, K, sA, sW, sC, rdiv);
    else if (epi == EPI_SCORES)
        gemm_tn<EPI_SCORES><<<grid, block>>>(A, W, C, M, N, K, sA, sW, sC, rdiv);
    else
        gemm_tn<EPI_DIV><<<grid, block>>>(A, W, C, M, N, K, sA, sW, sC, rdiv);
}

extern "C" void kernel_launch(void* const* d_in, const int* in_sizes, int n_in,
                              void* d_out, int out_size)
{
    const int*   ids   = (const int*)  d_in[0];
    const float* emb   = (const float*)d_in[1];
    const float* qkv_w = (const float*)d_in[2];
    const float* out_w = (const float*)d_in[3];
    const float* n1_w  = (const float*)d_in[4];
    const float* n2_w  = (const float*)d_in[5];
    const float* wm_w  = (const float*)d_in[6];
    const float* w3_w  = (const float*)d_in[7];
    const float* fn_w  = (const float*)d_in[8];
    float* logits = (float*)d_out;

    float *px, *pxn, *pqkv, *pq, *pk, *pvt, *ps4, *prs, *po, *pom, *ptmp, *phid;
    cudaGetSymbolAddress((void**)&px,   g_x);
    cudaGetSymbolAddress((void**)&pxn,  g_xn);
    cudaGetSymbolAddress((void**)&pqkv, g_qkv);
    cudaGetSymbolAddress((void**)&pq,   g_q);
    cudaGetSymbolAddress((void**)&pk,   g_k);
    cudaGetSymbolAddress((void**)&pvt,  g_vt);
    cudaGetSymbolAddress((void**)&ps4,  g_s4);
    cudaGetSymbolAddress((void**)&prs,  g_rs);
    cudaGetSymbolAddress((void**)&po,   g_o);
    cudaGetSymbolAddress((void**)&pom,  g_om);
    cudaGetSymbolAddress((void**)&ptmp, g_tmp);
    cudaGetSymbolAddress((void**)&phid, g_hid);

    const long long nXD = (long long)NTc * Dc;

    // embed
    embed_kernel<<<(unsigned)((nXD + 255) / 256), 256>>>(ids, emb);

    for (int l = 0; l < Lc; l++) {
        // ---- attention ----
        norm_kernel<<<NTc, 256>>>(px, n1_w + (long long)l * Dc, pxn);

        gemm_launch(EPI_NONE, pxn, qkv_w + (long long)l * 3 * Dc * Dc, pqkv,
                    NTc, 3 * Dc, Dc, 0, 0, 0, 1, nullptr);

        split_qkv_kernel<<<(unsigned)(((long long)NTc * 3 * Dc + 255) / 256), 256>>>();

        // scores + alibi + causal + sigmoid^4 fused epilogue
        gemm_launch(EPI_SCORES, pq, pk, ps4,
                    Tc, Tc, DHc,
                    (long long)Tc * DHc, (long long)Tc * DHc, (long long)Tc * Tc,
                    Bc * Hc, nullptr);

        rowsum_kernel<<<Bc * Hc * Tc, 256>>>();

        // (s4 @ V) / (rowsum + eps) fused epilogue
        gemm_launch(EPI_DIV, ps4, pvt, po,
                    Tc, DHc, Tc,
                    (long long)Tc * Tc, (long long)DHc * Tc, (long long)Tc * DHc,
                    Bc * Hc, prs);

        merge_heads_kernel<<<(unsigned)(((long long)Bc * Hc * Tc * DHc + 255) / 256), 256>>>();

        gemm_launch(EPI_NONE, pom, out_w + (long long)l * Dc * Dc, ptmp,
                    NTc, Dc, Dc, 0, 0, 0, 1, nullptr);

        add_kernel<<<(unsigned)((nXD + 255) / 256), 256>>>(ptmp, nXD);

        // ---- swiglu ffn ----
        norm_kernel<<<NTc, 256>>>(px, n2_w + (long long)l * Dc, pxn);

        gemm_launch(EPI_NONE, pxn, wm_w + (long long)l * 2 * DFFc * Dc, ptmp,
                    NTc, 2 * DFFc, Dc, 0, 0, 0, 1, nullptr);

        swiglu_kernel<<<(unsigned)(((long long)NTc * DFFc + 255) / 256), 256>>>();

        gemm_launch(EPI_NONE, phid, w3_w + (long long)l * Dc * DFFc, pom,
                    NTc, Dc, DFFc, 0, 0, 0, 1, nullptr);

        add_kernel<<<(unsigned)((nXD + 255) / 256), 256>>>(pom, nXD);
    }

    // ---- final norm + logits ----
    norm_kernel<<<NTc, 256>>>(px, fn_w, pxn);

    gemm_launch(EPI_NONE, pxn, emb, logits,
                NTc, Vc, Dc, 0, 0, 0, 1, nullptr);
}

// round 10
// speedup vs baseline: 2.1446x; 2.1446x over previous
#include <cuda_runtime.h>
#include <cuda_bf16.h>
#include <math.h>
#include <stdint.h>

// ---------------- problem constants ----------------
#define Bc   2
#define Tc   1024
#define Vc   32000
#define Dc   1024
#define Hc   16
#define Lc   4
#define DHc  64
#define DFFc 2730
#define NTc  (Bc*Tc)
#define EPSf 1e-6f

#define KP_D   3072      // 3*1024
#define KP_FF  8192      // pad(3*2730=8190 -> 8192)
#define KP_ATT 192       // 3*64

// ---------------- scratch (static device globals; no allocs) ----------------
__device__ float g_x  [NTc*Dc];
__device__ float g_qkv[NTc*3*Dc];
__device__ float g_tmp[(size_t)NTc*2*DFFc];
__device__ float g_rs [Bc*Hc*Tc];
__device__ __nv_bfloat16 g_a3[(size_t)NTc*KP_FF];          // activation split (A form: hi|lo|hi)
__device__ __nv_bfloat16 g_wb[(size_t)Vc*KP_D];            // weight split (B form: hi|hi|lo)
__device__ __nv_bfloat16 g_q3[(size_t)Bc*Hc*Tc*KP_ATT];    // A form
__device__ __nv_bfloat16 g_k3[(size_t)Bc*Hc*Tc*KP_ATT];    // B form
__device__ __nv_bfloat16 g_v3[(size_t)Bc*Hc*DHc*KP_D];     // B form, V^T [bz][d][3072]
__device__ __nv_bfloat16 g_s3[(size_t)Bc*Hc*Tc*KP_D];      // A form, s4 [bz][t][3072]

__device__ __forceinline__ float rsig(float x) {
    return 0.5f * (x / (fabsf(x) + 1.0f) + 1.0f);
}
__device__ __forceinline__ void split2(float v, __nv_bfloat16& hi, __nv_bfloat16& lo) {
    hi = __float2bfloat16(v);
    lo = __float2bfloat16(v - __bfloat162float(hi));
}
__device__ __forceinline__ uint32_t pack_bf2(float a, float b) {
    __nv_bfloat162 t = __floats2bfloat162_rn(a, b);
    return *reinterpret_cast<uint32_t*>(&t);
}

// ---------------- PTX helpers (sm_80+ baseline) ----------------
__device__ __forceinline__ uint32_t s2u(const void* p) {
    uint32_t a;
    asm("{ .reg .u64 t; cvta.to.shared.u64 t, %1; cvt.u32.u64 %0, t; }" : "=r"(a) : "l"(p));
    return a;
}
__device__ __forceinline__ void cp16(uint32_t dst, const void* src, bool pred) {
    int sz = pred ? 16 : 0;
    asm volatile("cp.async.cg.shared.global [%0], [%1], 16, %2;"
                 :: "r"(dst), "l"(src), "r"(sz) : "memory");
}
__device__ __forceinline__ void cp_commit() {
    asm volatile("cp.async.commit_group;" ::: "memory");
}
__device__ __forceinline__ void cp_wait1() {
    asm volatile("cp.async.wait_group 1;" ::: "memory");
}
__device__ __forceinline__ void cp_wait0() {
    asm volatile("cp.async.wait_group 0;" ::: "memory");
}
__device__ __forceinline__ void mma16816(float* c, const uint32_t* a, uint32_t b0, uint32_t b1) {
    asm volatile("mma.sync.aligned.m16n8k16.row.col.f32.bf16.bf16.f32 "
                 "{%0,%1,%2,%3}, {%4,%5,%6,%7}, {%8,%9}, {%0,%1,%2,%3};"
                 : "+f"(c[0]), "+f"(c[1]), "+f"(c[2]), "+f"(c[3])
                 : "r"(a[0]), "r"(a[1]), "r"(a[2]), "r"(a[3]), "r"(b0), "r"(b1));
}

// ---------------- HMMA GEMM: C[M,N] = A'[M,Kp] @ B'[N,Kp]^T ----------------
// BM=128 BN=128 BK=32. 2-stage cp.async double buffer. 8 warps (2m x 4n),
// warp tile 64x32. Padded (non-swizzled) smem: row stride 80B, direct u32
// fragment loads per the PTX mma.m16n8k16 fragment tables.
enum { EP_NONE = 0, EP_ADD = 1, EP_SCORES = 2, EP_PV = 3 };

#define SROW      80                  // smem row stride bytes (64B data + 16B pad)
#define TILE_BYT  (128 * SROW)        // 10240 per operand tile
#define STAGE_BYT (2 * TILE_BYT)      // A + B per stage

template<int EPI>
__global__ void __launch_bounds__(256)
gemm_mma(const __nv_bfloat16* __restrict__ A, const __nv_bfloat16* __restrict__ B,
         float* __restrict__ C, int M, int N, int Kp,
         long long sA, long long sB, const float* __restrict__ rdiv)
{
    __shared__ __align__(16) char smem[2 * STAGE_BYT];   // 40 KB static

    const int tid  = threadIdx.x;
    const int lane = tid & 31, wid = tid >> 5;
    const int wm   = wid >> 2, wn = wid & 3;
    const int bz   = blockIdx.z;
    const int m0   = blockIdx.x * 128;
    const int n0   = blockIdx.y * 128;

    const __nv_bfloat16* Ab = A + (long long)bz * sA + (long long)m0 * Kp;
    const __nv_bfloat16* Bb = B + (long long)bz * sB;

    const uint32_t sbase = s2u(smem);
    const int nk = Kp >> 5;

    // copy coords: 512 16B-chunks per tile (128 rows x 4 chunks), 2 per thread
    int cr[2], cc[2];
    #pragma unroll
    for (int i = 0; i < 2; i++) { int e = tid + i * 256; cr[i] = e >> 2; cc[i] = e & 3; }

    // ---- prologue: stage 0 ----
    {
        uint32_t da = sbase, db = sbase + TILE_BYT;
        #pragma unroll
        for (int i = 0; i < 2; i++) {
            const char* srcA = (const char*)(Ab + (long long)cr[i] * Kp) + cc[i] * 16;
            cp16(da + cr[i] * SROW + cc[i] * 16, srcA, true);
            bool v = (n0 + cr[i]) < N;
            int rB = v ? (n0 + cr[i]) : 0;
            const char* srcB = (const char*)(Bb + (long long)rB * Kp) + cc[i] * 16;
            cp16(db + cr[i] * SROW + cc[i] * 16, srcB, v);
        }
        cp_commit();
    }

    float acc[4][4][4] = {};

    for (int kt = 0; kt < nk; kt++) {
        const int nxt = kt + 1;
        if (nxt < nk) {
            uint32_t da = sbase + (nxt & 1) * STAGE_BYT;
            uint32_t db = da + TILE_BYT;
            #pragma unroll
            for (int i = 0; i < 2; i++) {
                const char* srcA = (const char*)(Ab + (long long)cr[i] * Kp + nxt * 32) + cc[i] * 16;
                cp16(da + cr[i] * SROW + cc[i] * 16, srcA, true);
                bool v = (n0 + cr[i]) < N;
                int rB = v ? (n0 + cr[i]) : 0;
                const char* srcB = (const char*)(Bb + (long long)rB * Kp + nxt * 32) + cc[i] * 16;
                cp16(db + cr[i] * SROW + cc[i] * 16, srcB, v);
            }
            cp_commit();
            cp_wait1();      // stage kt complete
        } else {
            cp_wait0();
        }
        __syncthreads();

        const char* sa = smem + (kt & 1) * STAGE_BYT;
        const char* sb = sa + TILE_BYT;

        #pragma unroll
        for (int ks = 0; ks < 2; ks++) {
            // A fragments per PTX m16n8k16 A table:
            // reg r: row = base + lane/4 + (r&1)*8 ; k = ks*16 + 2*(lane&3) + (r>>1)*8
            uint32_t af[4][4];
            #pragma unroll
            for (int fm = 0; fm < 4; fm++) {
                const int rbase = wm * 64 + fm * 16 + (lane >> 2);
                const int kb    = ks * 16 + 2 * (lane & 3);
                #pragma unroll
                for (int r = 0; r < 4; r++) {
                    int row = rbase + (r & 1) * 8;
                    int kk  = kb + (r >> 1) * 8;
                    af[fm][r] = *(const uint32_t*)(sa + row * SROW + kk * 2);
                }
            }
            // B fragments: reg r: n = base + lane/4 ; k = ks*16 + 2*(lane&3) + r*8
            uint32_t bf[2][2][2];
            #pragma unroll
            for (int fn = 0; fn < 2; fn++)
                #pragma unroll
                for (int sub = 0; sub < 2; sub++) {
                    const int n = wn * 32 + fn * 16 + sub * 8 + (lane >> 2);
                    const int kb = ks * 16 + 2 * (lane & 3);
                    #pragma unroll
                    for (int r = 0; r < 2; r++)
                        bf[fn][sub][r] = *(const uint32_t*)(sb + n * SROW + (kb + r * 8) * 2);
                }
            #pragma unroll
            for (int fm = 0; fm < 4; fm++)
                #pragma unroll
                for (int fn = 0; fn < 2; fn++)
                    #pragma unroll
                    for (int sub = 0; sub < 2; sub++)
                        mma16816(acc[fm][fn * 2 + sub], af[fm],
                                 bf[fn][sub][0], bf[fn][sub][1]);
        }
        __syncthreads();
    }

    // ---------------- epilogue ----------------
    #pragma unroll
    for (int fm = 0; fm < 4; fm++) {
        const int gmr = m0 + wm * 64 + fm * 16 + (lane >> 2);
        #pragma unroll
        for (int ng = 0; ng < 4; ng++) {
            const int gn = n0 + wn * 32 + ng * 8 + (lane & 3) * 2;
            #pragma unroll
            for (int hh = 0; hh < 2; hh++) {
                const int gm = gmr + hh * 8;
                float v0 = acc[fm][ng][2 * hh];
                float v1 = acc[fm][ng][2 * hh + 1];

                if (EPI == EP_SCORES) {
                    const int   hd    = bz & (Hc - 1);
                    const float slope = exp2f(-0.5f * (float)(hd + 1));
                    float s0 = v0 * 0.125f - slope * fabsf((float)(gm - gn));
                    float s1 = v1 * 0.125f - slope * fabsf((float)(gm - gn - 1));
                    if (gm < gn)     s0 = -10000.0f;
                    if (gm < gn + 1) s1 = -10000.0f;
                    float q0 = rsig(s0); q0 *= q0; s0 = q0 * q0;
                    float q1 = rsig(s1); q1 *= q1; s1 = q1 * q1;
                    __nv_bfloat16 h0, l0, h1, l1;
                    split2(s0, h0, l0); split2(s1, h1, l1);
                    // s3 is an A operand: [hi | lo | hi]
                    __nv_bfloat16* rowp = g_s3 + ((size_t)bz * Tc + gm) * KP_D;
                    uint32_t hp = pack_bf2(__bfloat162float(h0), __bfloat162float(h1));
                    uint32_t lp = pack_bf2(__bfloat162float(l0), __bfloat162float(l1));
                    *(uint32_t*)(rowp + gn)        = hp;
                    *(uint32_t*)(rowp + 1024 + gn) = lp;
                    *(uint32_t*)(rowp + 2048 + gn) = hp;
                } else if (EPI == EP_PV) {
                    if (gn >= N) continue;
                    const float inv = 1.0f / (rdiv[(size_t)bz * Tc + gm] + EPSf);
                    const int b = bz >> 4, hd = bz & 15;
                    float o0 = v0 * inv, o1 = v1 * inv;
                    __nv_bfloat16 h0, l0, h1, l1;
                    split2(o0, h0, l0); split2(o1, h1, l1);
                    // a3 is an A operand: [hi | lo | hi]
                    __nv_bfloat16* rowp = g_a3 + ((size_t)(b * Tc + gm)) * KP_D;
                    const int col = hd * DHc + gn;
                    uint32_t hp = pack_bf2(__bfloat162float(h0), __bfloat162float(h1));
                    uint32_t lp = pack_bf2(__bfloat162float(l0), __bfloat162float(l1));
                    *(uint32_t*)(rowp + col)        = hp;
                    *(uint32_t*)(rowp + 1024 + col) = lp;
                    *(uint32_t*)(rowp + 2048 + col) = hp;
                } else {
                    if (gn >= N) continue;
                    float* cp = C + (size_t)gm * N + gn;
                    if (EPI == EP_ADD) { cp[0] += v0; cp[1] += v1; }
                    else {
                        float2 t; t.x = v0; t.y = v1;
                        *(float2*)cp = t;
                    }
                }
            }
        }
    }
}

// ---------------- elementwise / reduction kernels ----------------

__global__ void embed_kernel(const int* __restrict__ ids, const float* __restrict__ emb)
{
    long long idx = (long long)blockIdx.x * blockDim.x + threadIdx.x;
    if (idx >= (long long)NTc * Dc) return;
    int tok = (int)(idx / Dc);
    int d   = (int)(idx % Dc);
    g_x[idx] = emb[(long long)ids[tok] * Dc + d];
}

// mean-error norm -> A-form split row [hi | lo | hi] at given stride
__global__ void __launch_bounds__(256)
norm_split_kernel(const float* __restrict__ x, const float* __restrict__ w, int stride)
{
    int row = blockIdx.x;
    const float* xr = x + (long long)row * Dc;
    float s = 0.0f;
    for (int d = threadIdx.x; d < Dc; d += 256) s += fabsf(xr[d]);
    #pragma unroll
    for (int off = 16; off > 0; off >>= 1) s += __shfl_xor_sync(0xffffffffu, s, off);
    __shared__ float red[8];
    int wid = threadIdx.x >> 5, lid = threadIdx.x & 31;
    if (lid == 0) red[wid] = s;
    __syncthreads();
    __shared__ float s_inv;
    if (threadIdx.x == 0) {
        float t = 0.0f;
        #pragma unroll
        for (int i = 0; i < 8; i++) t += red[i];
        s_inv = 1.0f / (t * (1.0f / Dc) + EPSf);
    }
    __syncthreads();
    float inv = s_inv;
    __nv_bfloat16* orow = g_a3 + (size_t)row * stride;
    for (int d = threadIdx.x; d < Dc; d += 256) {
        float v = xr[d] * inv * w[d];
        __nv_bfloat16 hi, lo; split2(v, hi, lo);
        orow[d] = hi; orow[1024 + d] = lo; orow[2048 + d] = hi;
    }
}

// weight fp32 [N,K] -> B-form bf16 split [N,Kp]: [hi K | hi K | lo K | zeros]
__global__ void wcvt_kernel(const float* __restrict__ src, __nv_bfloat16* __restrict__ dst,
                            int N, int K, int Kp)
{
    long long idx = (long long)blockIdx.x * blockDim.x + threadIdx.x;
    if (idx >= (long long)N * Kp) return;
    int n = (int)(idx / Kp);
    int c = (int)(idx % Kp);
    __nv_bfloat16 o;
    if (c < 3 * K) {
        int cc = (c < K) ? c : ((c < 2 * K) ? c - K : c - 2 * K);
        float v = src[(long long)n * K + cc];
        __nv_bfloat16 hi, lo; split2(v, hi, lo);
        o = (c >= 2 * K) ? lo : hi;      // B form: segments [hi | hi | lo]
    } else {
        o = __float2bfloat16(0.0f);
    }
    dst[idx] = o;
}

// split qkv fp32 [tok][3072]:
//   q3 (A operand) -> [hi | lo | hi]
//   k3 (B operand) -> [hi | hi | lo]
//   v3 (B operand, transposed) -> [hi | hi | lo]
__global__ void split_qkv_kernel()
{
    long long idx = (long long)blockIdx.x * blockDim.x + threadIdx.x;
    if (idx >= (long long)NTc * 3 * Dc) return;
    int tok = (int)(idx / (3 * Dc));
    int r   = (int)(idx % (3 * Dc));
    int c   = r / Dc;
    int hd  = r % Dc;
    int h   = hd / DHc;
    int d   = hd % DHc;
    int b   = tok / Tc;
    int t   = tok % Tc;
    float v = g_qkv[idx];
    __nv_bfloat16 hi, lo; split2(v, hi, lo);
    size_t bz = (size_t)(b * Hc + h);
    if (c == 0) {
        __nv_bfloat16* rp = g_q3 + (bz * Tc + t) * KP_ATT;
        rp[d] = hi; rp[64 + d] = lo; rp[128 + d] = hi;       // A form
    } else if (c == 1) {
        __nv_bfloat16* rp = g_k3 + (bz * Tc + t) * KP_ATT;
        rp[d] = hi; rp[64 + d] = hi; rp[128 + d] = lo;       // B form
    } else {
        __nv_bfloat16* rp = g_v3 + (bz * DHc + d) * KP_D;
        rp[t] = hi; rp[1024 + t] = hi; rp[2048 + t] = lo;    // B form
    }
}

// rowsum of s4 from A-form split (hi at +0, lo at +1024)
__global__ void __launch_bounds__(256)
rowsum_kernel()
{
    int row = blockIdx.x;                   // 0 .. B*H*T-1
    const __nv_bfloat16* sr = g_s3 + (size_t)row * KP_D;
    float s = 0.0f;
    for (int j = threadIdx.x; j < Tc; j += 256)
        s += __bfloat162float(sr[j]) + __bfloat162float(sr[1024 + j]);
    #pragma unroll
    for (int off = 16; off > 0; off >>= 1) s += __shfl_xor_sync(0xffffffffu, s, off);
    __shared__ float red[8];
    int wid = threadIdx.x >> 5, lid = threadIdx.x & 31;
    if (lid == 0) red[wid] = s;
    __syncthreads();
    if (threadIdx.x == 0) {
        float t = 0.0f;
        #pragma unroll
        for (int i = 0; i < 8; i++) t += red[i];
        g_rs[row] = t;
    }
}

// swiglu: reads g_tmp [tok][5460], writes A-form split rows into g_a3 at stride 8192
__global__ void swiglu_kernel()
{
    long long idx = (long long)blockIdx.x * blockDim.x + threadIdx.x;
    if (idx >= (long long)NTc * DFFc) return;
    int tok = (int)(idx / DFFc);
    int j   = (int)(idx % DFFc);
    float g = g_tmp[(long long)tok * (2 * DFFc) + j];
    float v = g_tmp[(long long)tok * (2 * DFFc) + DFFc + j];
    float o = g * rsig(g) * v;
    __nv_bfloat16 hi, lo; split2(o, hi, lo);
    __nv_bfloat16* rp = g_a3 + (size_t)tok * KP_FF;
    rp[j] = hi; rp[DFFc + j] = lo; rp[2 * DFFc + j] = hi;
    if (j < 2) rp[3 * DFFc + j] = __float2bfloat16(0.0f);   // pad cols 8190/8191
}

// ---------------- host ----------------

template<int EPI>
static void launch_gemm(const __nv_bfloat16* A, const __nv_bfloat16* B, float* C,
                        int M, int N, int Kp, long long sA, long long sB,
                        int batch, const float* rdiv)
{
    dim3 grid(M / 128, (N + 127) / 128, batch);
    gemm_mma<EPI><<<grid, 256>>>(A, B, C, M, N, Kp, sA, sB, rdiv);
}

extern "C" void kernel_launch(void* const* d_in, const int* in_sizes, int n_in,
                              void* d_out, int out_size)
{
    const int*   ids   = (const int*)  d_in[0];
    const float* emb   = (const float*)d_in[1];
    const float* qkv_w = (const float*)d_in[2];
    const float* out_w = (const float*)d_in[3];
    const float* n1_w  = (const float*)d_in[4];
    const float* n2_w  = (const float*)d_in[5];
    const float* wm_w  = (const float*)d_in[6];
    const float* w3_w  = (const float*)d_in[7];
    const float* fn_w  = (const float*)d_in[8];
    float* logits = (float*)d_out;

    float *px, *pqkv, *ptmp, *prs;
    __nv_bfloat16 *pa3, *pwb, *pq3, *pk3, *pv3, *ps3;
    cudaGetSymbolAddress((void**)&px,   g_x);
    cudaGetSymbolAddress((void**)&pqkv, g_qkv);
    cudaGetSymbolAddress((void**)&ptmp, g_tmp);
    cudaGetSymbolAddress((void**)&prs,  g_rs);
    cudaGetSymbolAddress((void**)&pa3,  g_a3);
    cudaGetSymbolAddress((void**)&pwb,  g_wb);
    cudaGetSymbolAddress((void**)&pq3,  g_q3);
    cudaGetSymbolAddress((void**)&pk3,  g_k3);
    cudaGetSymbolAddress((void**)&pv3,  g_v3);
    cudaGetSymbolAddress((void**)&ps3,  g_s3);

    const long long nXD = (long long)NTc * Dc;

    embed_kernel<<<(unsigned)((nXD + 255) / 256), 256>>>(ids, emb);

    for (int l = 0; l < Lc; l++) {
        // ---- attention ----
        norm_split_kernel<<<NTc, 256>>>(px, n1_w + (long long)l * Dc, KP_D);

        wcvt_kernel<<<(unsigned)(((long long)3 * Dc * KP_D + 255) / 256), 256>>>(
            qkv_w + (long long)l * 3 * Dc * Dc, pwb, 3 * Dc, Dc, KP_D);
        launch_gemm<EP_NONE>(pa3, pwb, pqkv, NTc, 3 * Dc, KP_D, 0, 0, 1, nullptr);

        split_qkv_kernel<<<(unsigned)(((long long)NTc * 3 * Dc + 255) / 256), 256>>>();

        // scores + alibi + causal + sigmoid^4 -> split bf16
        launch_gemm<EP_SCORES>(pq3, pk3, nullptr, Tc, Tc, KP_ATT,
                               (long long)Tc * KP_ATT, (long long)Tc * KP_ATT,
                               Bc * Hc, nullptr);

        rowsum_kernel<<<Bc * Hc * Tc, 256>>>();

        // (s4 @ V) / rowsum -> merged-head split directly into a3
        launch_gemm<EP_PV>(ps3, pv3, nullptr, Tc, DHc, KP_D,
                           (long long)Tc * KP_D, (long long)DHc * KP_D,
                           Bc * Hc, prs);

        wcvt_kernel<<<(unsigned)(((long long)Dc * KP_D + 255) / 256), 256>>>(
            out_w + (long long)l * Dc * Dc, pwb, Dc, Dc, KP_D);
        launch_gemm<EP_ADD>(pa3, pwb, px, NTc, Dc, KP_D, 0, 0, 1, nullptr);

        // ---- swiglu ffn ----
        norm_split_kernel<<<NTc, 256>>>(px, n2_w + (long long)l * Dc, KP_D);

        wcvt_kernel<<<(unsigned)(((long long)2 * DFFc * KP_D + 255) / 256), 256>>>(
            wm_w + (long long)l * 2 * DFFc * Dc, pwb, 2 * DFFc, Dc, KP_D);
        launch_gemm<EP_NONE>(pa3, pwb, ptmp, NTc, 2 * DFFc, KP_D, 0, 0, 1, nullptr);

        swiglu_kernel<<<(unsigned)(((long long)NTc * DFFc + 255) / 256), 256>>>();

        wcvt_kernel<<<(unsigned)(((long long)Dc * KP_FF + 255) / 256), 256>>>(
            w3_w + (long long)l * Dc * DFFc, pwb, Dc, DFFc, KP_FF);
        launch_gemm<EP_ADD>(pa3, pwb, px, NTc, Dc, KP_FF, 0, 0, 1, nullptr);
    }

    // ---- final norm + logits ----
    norm_split_kernel<<<NTc, 256>>>(px, fn_w, KP_D);

    wcvt_kernel<<<(unsigned)(((long long)Vc * KP_D + 255) / 256), 256>>>(
        emb, pwb, Vc, Dc, KP_D);
    launch_gemm<EP_NONE>(pa3, pwb, logits, NTc, Vc, KP_D, 0, 0, 1, nullptr);
}

// round 11
// speedup vs baseline: 2.5319x; 1.1806x over previous
#include <cuda_runtime.h>
#include <cuda_bf16.h>
#include <math.h>
#include <stdint.h>

// ---------------- problem constants ----------------
#define Bc   2
#define Tc   1024
#define Vc   32000
#define Dc   1024
#define Hc   16
#define Lc   4
#define DHc  64
#define DFFc 2730
#define NTc  (Bc*Tc)
#define EPSf 1e-6f

#define KP_D   3072      // 3*1024
#define KP_FF  8192      // pad(3*2730=8190 -> 8192)
#define KP_ATT 192       // 3*64

// ---------------- scratch (static device globals; no allocs) ----------------
__device__ float g_x  [NTc*Dc];
__device__ float g_qkv[NTc*3*Dc];
__device__ float g_tmp[(size_t)NTc*2*DFFc];
__device__ float g_rs [Bc*Hc*Tc];
__device__ __nv_bfloat16 g_a3[(size_t)NTc*KP_FF];          // activation split (A form: hi|lo|hi)
__device__ __nv_bfloat16 g_wb[(size_t)Vc*KP_D];            // weight split (B form: hi|hi|lo)
__device__ __nv_bfloat16 g_q3[(size_t)Bc*Hc*Tc*KP_ATT];    // A form
__device__ __nv_bfloat16 g_k3[(size_t)Bc*Hc*Tc*KP_ATT];    // B form
__device__ __nv_bfloat16 g_v3[(size_t)Bc*Hc*DHc*KP_D];     // B form, V^T [bz][d][3072]
__device__ __nv_bfloat16 g_s3[(size_t)Bc*Hc*Tc*KP_D];      // A form, s4 [bz][t][3072]

__device__ __forceinline__ float rsig(float x) {
    return 0.5f * (x / (fabsf(x) + 1.0f) + 1.0f);
}
__device__ __forceinline__ void split2(float v, __nv_bfloat16& hi, __nv_bfloat16& lo) {
    hi = __float2bfloat16(v);
    lo = __float2bfloat16(v - __bfloat162float(hi));
}
__device__ __forceinline__ uint32_t pack_bf2(float a, float b) {
    __nv_bfloat162 t = __floats2bfloat162_rn(a, b);
    return *reinterpret_cast<uint32_t*>(&t);
}

// ---------------- PTX helpers (sm_80+ baseline) ----------------
__device__ __forceinline__ uint32_t s2u(const void* p) {
    uint32_t a;
    asm("{ .reg .u64 t; cvta.to.shared.u64 t, %1; cvt.u32.u64 %0, t; }" : "=r"(a) : "l"(p));
    return a;
}
__device__ __forceinline__ void cp16(uint32_t dst, const void* src, bool pred) {
    int sz = pred ? 16 : 0;
    asm volatile("cp.async.cg.shared.global [%0], [%1], 16, %2;"
                 :: "r"(dst), "l"(src), "r"(sz) : "memory");
}
__device__ __forceinline__ void cp_commit() {
    asm volatile("cp.async.commit_group;" ::: "memory");
}
__device__ __forceinline__ void cp_wait1() {
    asm volatile("cp.async.wait_group 1;" ::: "memory");
}
__device__ __forceinline__ void mma16816(float* c, const uint32_t* a, uint32_t b0, uint32_t b1) {
    asm volatile("mma.sync.aligned.m16n8k16.row.col.f32.bf16.bf16.f32 "
                 "{%0,%1,%2,%3}, {%4,%5,%6,%7}, {%8,%9}, {%0,%1,%2,%3};"
                 : "+f"(c[0]), "+f"(c[1]), "+f"(c[2]), "+f"(c[3])
                 : "r"(a[0]), "r"(a[1]), "r"(a[2]), "r"(a[3]), "r"(b0), "r"(b1));
}

// ---------------- HMMA GEMM: C[M,N] = A'[M,Kp] @ B'[N,Kp]^T ----------------
// BM=128 BN=128 BK=64. 3-stage cp.async pipeline, ONE __syncthreads per k-iter.
// 8 warps (2m x 4n), warp tile 64x32. Padded smem rows (144B), direct u32
// fragment loads per the PTX mma.m16n8k16 fragment tables.
enum { EP_NONE = 0, EP_ADD = 1, EP_SCORES = 2, EP_PV = 3 };

#define BKc       64
#define SROW      144                 // 128B data + 16B pad
#define TILE_BYT  (128 * SROW)        // 18432 per operand tile
#define STAGE_BYT (2 * TILE_BYT)      // A + B per stage
#define NSTG      3
#define SMEM_TOT  (NSTG * STAGE_BYT)  // 110592

template<int EPI>
__global__ void __launch_bounds__(256)
gemm_mma(const __nv_bfloat16* __restrict__ A, const __nv_bfloat16* __restrict__ B,
         float* __restrict__ C, int M, int N, int Kp,
         long long sA, long long sB, const float* __restrict__ rdiv)
{
    extern __shared__ __align__(16) char smem[];

    const int tid  = threadIdx.x;
    const int lane = tid & 31, wid = tid >> 5;
    const int wm   = wid >> 2, wn = wid & 3;
    const int bz   = blockIdx.z;
    const int m0   = blockIdx.x * 128;
    const int n0   = blockIdx.y * 128;

    const __nv_bfloat16* Ab = A + (long long)bz * sA + (long long)m0 * Kp;
    const __nv_bfloat16* Bb = B + (long long)bz * sB;

    const uint32_t sbase = s2u(smem);
    const int nk = Kp >> 6;

    // copy coords: 1024 16B-chunks per tile (128 rows x 8 chunks), 4 per thread
    int cr[4], cc[4];
    #pragma unroll
    for (int i = 0; i < 4; i++) { int e = tid + i * 256; cr[i] = e >> 3; cc[i] = e & 7; }

    // ---- prologue: stages 0..NSTG-2 ----
    #pragma unroll
    for (int s = 0; s < NSTG - 1; s++) {
        if (s < nk) {
            uint32_t da = sbase + s * STAGE_BYT;
            uint32_t db = da + TILE_BYT;
            #pragma unroll
            for (int i = 0; i < 4; i++) {
                const char* srcA = (const char*)(Ab + (long long)cr[i] * Kp + s * BKc) + cc[i] * 16;
                cp16(da + cr[i] * SROW + cc[i] * 16, srcA, true);
                bool v = (n0 + cr[i]) < N;
                int rB = v ? (n0 + cr[i]) : 0;
                const char* srcB = (const char*)(Bb + (long long)rB * Kp + s * BKc) + cc[i] * 16;
                cp16(db + cr[i] * SROW + cc[i] * 16, srcB, v);
            }
        }
        cp_commit();
    }

    float acc[4][4][4] = {};

    for (int kt = 0; kt < nk; kt++) {
        cp_wait1();        // stage kt complete (one newer group may stay pending)
        __syncthreads();   // all warps done reading buf[(kt-1)%NSTG] (overwritten next)

        // prefetch stage kt+NSTG-1 into buffer last read at iter kt-1
        const int nxt = kt + NSTG - 1;
        if (nxt < nk) {
            uint32_t da = sbase + (nxt % NSTG) * STAGE_BYT;
            uint32_t db = da + TILE_BYT;
            #pragma unroll
            for (int i = 0; i < 4; i++) {
                const char* srcA = (const char*)(Ab + (long long)cr[i] * Kp + nxt * BKc) + cc[i] * 16;
                cp16(da + cr[i] * SROW + cc[i] * 16, srcA, true);
                bool v = (n0 + cr[i]) < N;
                int rB = v ? (n0 + cr[i]) : 0;
                const char* srcB = (const char*)(Bb + (long long)rB * Kp + nxt * BKc) + cc[i] * 16;
                cp16(db + cr[i] * SROW + cc[i] * 16, srcB, v);
            }
        }
        cp_commit();       // empty-group commits keep wait_group accounting uniform

        const char* sa = smem + (kt % NSTG) * STAGE_BYT;
        const char* sb = sa + TILE_BYT;

        #pragma unroll
        for (int ks = 0; ks < 4; ks++) {
            // A fragments per PTX m16n8k16 A table:
            // reg r: row = base + lane/4 + (r&1)*8 ; k = ks*16 + 2*(lane&3) + (r>>1)*8
            uint32_t af[4][4];
            #pragma unroll
            for (int fm = 0; fm < 4; fm++) {
                const int rbase = wm * 64 + fm * 16 + (lane >> 2);
                const int kb    = ks * 16 + 2 * (lane & 3);
                #pragma unroll
                for (int r = 0; r < 4; r++) {
                    int row = rbase + (r & 1) * 8;
                    int kk  = kb + (r >> 1) * 8;
                    af[fm][r] = *(const uint32_t*)(sa + row * SROW + kk * 2);
                }
            }
            // B fragments: reg r: n = base + lane/4 ; k = ks*16 + 2*(lane&3) + r*8
            uint32_t bf[2][2][2];
            #pragma unroll
            for (int fn = 0; fn < 2; fn++)
                #pragma unroll
                for (int sub = 0; sub < 2; sub++) {
                    const int n = wn * 32 + fn * 16 + sub * 8 + (lane >> 2);
                    const int kb = ks * 16 + 2 * (lane & 3);
                    #pragma unroll
                    for (int r = 0; r < 2; r++)
                        bf[fn][sub][r] = *(const uint32_t*)(sb + n * SROW + (kb + r * 8) * 2);
                }
            #pragma unroll
            for (int fm = 0; fm < 4; fm++)
                #pragma unroll
                for (int fn = 0; fn < 2; fn++)
                    #pragma unroll
                    for (int sub = 0; sub < 2; sub++)
                        mma16816(acc[fm][fn * 2 + sub], af[fm],
                                 bf[fn][sub][0], bf[fn][sub][1]);
        }
    }

    // ---------------- epilogue ----------------
    #pragma unroll
    for (int fm = 0; fm < 4; fm++) {
        const int gmr = m0 + wm * 64 + fm * 16 + (lane >> 2);
        #pragma unroll
        for (int ng = 0; ng < 4; ng++) {
            const int gn = n0 + wn * 32 + ng * 8 + (lane & 3) * 2;
            #pragma unroll
            for (int hh = 0; hh < 2; hh++) {
                const int gm = gmr + hh * 8;
                float v0 = acc[fm][ng][2 * hh];
                float v1 = acc[fm][ng][2 * hh + 1];

                if (EPI == EP_SCORES) {
                    const int   hd    = bz & (Hc - 1);
                    const float slope = exp2f(-0.5f * (float)(hd + 1));
                    float s0 = v0 * 0.125f - slope * fabsf((float)(gm - gn));
                    float s1 = v1 * 0.125f - slope * fabsf((float)(gm - gn - 1));
                    if (gm < gn)     s0 = -10000.0f;
                    if (gm < gn + 1) s1 = -10000.0f;
                    float q0 = rsig(s0); q0 *= q0; s0 = q0 * q0;
                    float q1 = rsig(s1); q1 *= q1; s1 = q1 * q1;
                    __nv_bfloat16 h0, l0, h1, l1;
                    split2(s0, h0, l0); split2(s1, h1, l1);
                    // s3 is an A operand: [hi | lo | hi]
                    __nv_bfloat16* rowp = g_s3 + ((size_t)bz * Tc + gm) * KP_D;
                    uint32_t hp = pack_bf2(__bfloat162float(h0), __bfloat162float(h1));
                    uint32_t lp = pack_bf2(__bfloat162float(l0), __bfloat162float(l1));
                    *(uint32_t*)(rowp + gn)        = hp;
                    *(uint32_t*)(rowp + 1024 + gn) = lp;
                    *(uint32_t*)(rowp + 2048 + gn) = hp;
                } else if (EPI == EP_PV) {
                    if (gn >= N) continue;
                    const float inv = 1.0f / (rdiv[(size_t)bz * Tc + gm] + EPSf);
                    const int b = bz >> 4, hd = bz & 15;
                    float o0 = v0 * inv, o1 = v1 * inv;
                    __nv_bfloat16 h0, l0, h1, l1;
                    split2(o0, h0, l0); split2(o1, h1, l1);
                    // a3 is an A operand: [hi | lo | hi]
                    __nv_bfloat16* rowp = g_a3 + ((size_t)(b * Tc + gm)) * KP_D;
                    const int col = hd * DHc + gn;
                    uint32_t hp = pack_bf2(__bfloat162float(h0), __bfloat162float(h1));
                    uint32_t lp = pack_bf2(__bfloat162float(l0), __bfloat162float(l1));
                    *(uint32_t*)(rowp + col)        = hp;
                    *(uint32_t*)(rowp + 1024 + col) = lp;
                    *(uint32_t*)(rowp + 2048 + col) = hp;
                } else {
                    if (gn >= N) continue;
                    float* cp = C + (size_t)gm * N + gn;
                    if (EPI == EP_ADD) { cp[0] += v0; cp[1] += v1; }
                    else {
                        float2 t; t.x = v0; t.y = v1;
                        *(float2*)cp = t;
                    }
                }
            }
        }
    }
}

// ---------------- elementwise / reduction kernels ----------------

__global__ void embed_kernel(const int* __restrict__ ids, const float* __restrict__ emb)
{
    long long idx = (long long)blockIdx.x * blockDim.x + threadIdx.x;
    if (idx >= (long long)NTc * Dc) return;
    int tok = (int)(idx / Dc);
    int d   = (int)(idx % Dc);
    g_x[idx] = emb[(long long)ids[tok] * Dc + d];
}

// mean-error norm -> A-form split row [hi | lo | hi] at given stride
__global__ void __launch_bounds__(256)
norm_split_kernel(const float* __restrict__ x, const float* __restrict__ w, int stride)
{
    int row = blockIdx.x;
    const float* xr = x + (long long)row * Dc;
    float s = 0.0f;
    for (int d = threadIdx.x; d < Dc; d += 256) s += fabsf(xr[d]);
    #pragma unroll
    for (int off = 16; off > 0; off >>= 1) s += __shfl_xor_sync(0xffffffffu, s, off);
    __shared__ float red[8];
    int wid = threadIdx.x >> 5, lid = threadIdx.x & 31;
    if (lid == 0) red[wid] = s;
    __syncthreads();
    __shared__ float s_inv;
    if (threadIdx.x == 0) {
        float t = 0.0f;
        #pragma unroll
        for (int i = 0; i < 8; i++) t += red[i];
        s_inv = 1.0f / (t * (1.0f / Dc) + EPSf);
    }
    __syncthreads();
    float inv = s_inv;
    __nv_bfloat16* orow = g_a3 + (size_t)row * stride;
    for (int d = threadIdx.x; d < Dc; d += 256) {
        float v = xr[d] * inv * w[d];
        __nv_bfloat16 hi, lo; split2(v, hi, lo);
        orow[d] = hi; orow[1024 + d] = lo; orow[2048 + d] = hi;
    }
}

// weight fp32 [N,K] -> B-form bf16 split [N,Kp]: [hi K | hi K | lo K | zeros]
__global__ void wcvt_kernel(const float* __restrict__ src, __nv_bfloat16* __restrict__ dst,
                            int N, int K, int Kp)
{
    long long idx = (long long)blockIdx.x * blockDim.x + threadIdx.x;
    if (idx >= (long long)N * Kp) return;
    int n = (int)(idx / Kp);
    int c = (int)(idx % Kp);
    __nv_bfloat16 o;
    if (c < 3 * K) {
        int cc = (c < K) ? c : ((c < 2 * K) ? c - K : c - 2 * K);
        float v = src[(long long)n * K + cc];
        __nv_bfloat16 hi, lo; split2(v, hi, lo);
        o = (c >= 2 * K) ? lo : hi;      // B form: segments [hi | hi | lo]
    } else {
        o = __float2bfloat16(0.0f);
    }
    dst[idx] = o;
}

// split qkv fp32 [tok][3072]:
//   q3 (A operand) -> [hi | lo | hi]
//   k3 (B operand) -> [hi | hi | lo]
//   v3 (B operand, transposed) -> [hi | hi | lo]
__global__ void split_qkv_kernel()
{
    long long idx = (long long)blockIdx.x * blockDim.x + threadIdx.x;
    if (idx >= (long long)NTc * 3 * Dc) return;
    int tok = (int)(idx / (3 * Dc));
    int r   = (int)(idx % (3 * Dc));
    int c   = r / Dc;
    int hd  = r % Dc;
    int h   = hd / DHc;
    int d   = hd % DHc;
    int b   = tok / Tc;
    int t   = tok % Tc;
    float v = g_qkv[idx];
    __nv_bfloat16 hi, lo; split2(v, hi, lo);
    size_t bz = (size_t)(b * Hc + h);
    if (c == 0) {
        __nv_bfloat16* rp = g_q3 + (bz * Tc + t) * KP_ATT;
        rp[d] = hi; rp[64 + d] = lo; rp[128 + d] = hi;       // A form
    } else if (c == 1) {
        __nv_bfloat16* rp = g_k3 + (bz * Tc + t) * KP_ATT;
        rp[d] = hi; rp[64 + d] = hi; rp[128 + d] = lo;       // B form
    } else {
        __nv_bfloat16* rp = g_v3 + (bz * DHc + d) * KP_D;
        rp[t] = hi; rp[1024 + t] = hi; rp[2048 + t] = lo;    // B form
    }
}

// rowsum of s4 from A-form split (hi at +0, lo at +1024)
__global__ void __launch_bounds__(256)
rowsum_kernel()
{
    int row = blockIdx.x;                   // 0 .. B*H*T-1
    const __nv_bfloat16* sr = g_s3 + (size_t)row * KP_D;
    float s = 0.0f;
    for (int j = threadIdx.x; j < Tc; j += 256)
        s += __bfloat162float(sr[j]) + __bfloat162float(sr[1024 + j]);
    #pragma unroll
    for (int off = 16; off > 0; off >>= 1) s += __shfl_xor_sync(0xffffffffu, s, off);
    __shared__ float red[8];
    int wid = threadIdx.x >> 5, lid = threadIdx.x & 31;
    if (lid == 0) red[wid] = s;
    __syncthreads();
    if (threadIdx.x == 0) {
        float t = 0.0f;
        #pragma unroll
        for (int i = 0; i < 8; i++) t += red[i];
        g_rs[row] = t;
    }
}

// swiglu: reads g_tmp [tok][5460], writes A-form split rows into g_a3 at stride 8192
__global__ void swiglu_kernel()
{
    long long idx = (long long)blockIdx.x * blockDim.x + threadIdx.x;
    if (idx >= (long long)NTc * DFFc) return;
    int tok = (int)(idx / DFFc);
    int j   = (int)(idx % DFFc);
    float g = g_tmp[(long long)tok * (2 * DFFc) + j];
    float v = g_tmp[(long long)tok * (2 * DFFc) + DFFc + j];
    float o = g * rsig(g) * v;
    __nv_bfloat16 hi, lo; split2(o, hi, lo);
    __nv_bfloat16* rp = g_a3 + (size_t)tok * KP_FF;
    rp[j] = hi; rp[DFFc + j] = lo; rp[2 * DFFc + j] = hi;
    if (j < 2) rp[3 * DFFc + j] = __float2bfloat16(0.0f);   // pad cols 8190/8191
}

// ---------------- host ----------------

template<int EPI>
static void launch_gemm(const __nv_bfloat16* A, const __nv_bfloat16* B, float* C,
                        int M, int N, int Kp, long long sA, long long sB,
                        int batch, const float* rdiv)
{
    cudaFuncSetAttribute(gemm_mma<EPI>, cudaFuncAttributeMaxDynamicSharedMemorySize, SMEM_TOT);
    dim3 grid(M / 128, (N + 127) / 128, batch);
    gemm_mma<EPI><<<grid, 256, SMEM_TOT>>>(A, B, C, M, N, Kp, sA, sB, rdiv);
}

extern "C" void kernel_launch(void* const* d_in, const int* in_sizes, int n_in,
                              void* d_out, int out_size)
{
    const int*   ids   = (const int*)  d_in[0];
    const float* emb   = (const float*)d_in[1];
    const float* qkv_w = (const float*)d_in[2];
    const float* out_w = (const float*)d_in[3];
    const float* n1_w  = (const float*)d_in[4];
    const float* n2_w  = (const float*)d_in[5];
    const float* wm_w  = (const float*)d_in[6];
    const float* w3_w  = (const float*)d_in[7];
    const float* fn_w  = (const float*)d_in[8];
    float* logits = (float*)d_out;

    float *px, *pqkv, *ptmp, *prs;
    __nv_bfloat16 *pa3, *pwb, *pq3, *pk3, *pv3, *ps3;
    cudaGetSymbolAddress((void**)&px,   g_x);
    cudaGetSymbolAddress((void**)&pqkv, g_qkv);
    cudaGetSymbolAddress((void**)&ptmp, g_tmp);
    cudaGetSymbolAddress((void**)&prs,  g_rs);
    cudaGetSymbolAddress((void**)&pa3,  g_a3);
    cudaGetSymbolAddress((void**)&pwb,  g_wb);
    cudaGetSymbolAddress((void**)&pq3,  g_q3);
    cudaGetSymbolAddress((void**)&pk3,  g_k3);
    cudaGetSymbolAddress((void**)&pv3,  g_v3);
    cudaGetSymbolAddress((void**)&ps3,  g_s3);

    const long long nXD = (long long)NTc * Dc;

    embed_kernel<<<(unsigned)((nXD + 255) / 256), 256>>>(ids, emb);

    for (int l = 0; l < Lc; l++) {
        // ---- attention ----
        norm_split_kernel<<<NTc, 256>>>(px, n1_w + (long long)l * Dc, KP_D);

        wcvt_kernel<<<(unsigned)(((long long)3 * Dc * KP_D + 255) / 256), 256>>>(
            qkv_w + (long long)l * 3 * Dc * Dc, pwb, 3 * Dc, Dc, KP_D);
        launch_gemm<EP_NONE>(pa3, pwb, pqkv, NTc, 3 * Dc, KP_D, 0, 0, 1, nullptr);

        split_qkv_kernel<<<(unsigned)(((long long)NTc * 3 * Dc + 255) / 256), 256>>>();

        // scores + alibi + causal + sigmoid^4 -> split bf16
        launch_gemm<EP_SCORES>(pq3, pk3, nullptr, Tc, Tc, KP_ATT,
                               (long long)Tc * KP_ATT, (long long)Tc * KP_ATT,
                               Bc * Hc, nullptr);

        rowsum_kernel<<<Bc * Hc * Tc, 256>>>();

        // (s4 @ V) / rowsum -> merged-head split directly into a3
        launch_gemm<EP_PV>(ps3, pv3, nullptr, Tc, DHc, KP_D,
                           (long long)Tc * KP_D, (long long)DHc * KP_D,
                           Bc * Hc, prs);

        wcvt_kernel<<<(unsigned)(((long long)Dc * KP_D + 255) / 256), 256>>>(
            out_w + (long long)l * Dc * Dc, pwb, Dc, Dc, KP_D);
        launch_gemm<EP_ADD>(pa3, pwb, px, NTc, Dc, KP_D, 0, 0, 1, nullptr);

        // ---- swiglu ffn ----
        norm_split_kernel<<<NTc, 256>>>(px, n2_w + (long long)l * Dc, KP_D);

        wcvt_kernel<<<(unsigned)(((long long)2 * DFFc * KP_D + 255) / 256), 256>>>(
            wm_w + (long long)l * 2 * DFFc * Dc, pwb, 2 * DFFc, Dc, KP_D);
        launch_gemm<EP_NONE>(pa3, pwb, ptmp, NTc, 2 * DFFc, KP_D, 0, 0, 1, nullptr);

        swiglu_kernel<<<(unsigned)(((long long)NTc * DFFc + 255) / 256), 256>>>();

        wcvt_kernel<<<(unsigned)(((long long)Dc * KP_FF + 255) / 256), 256>>>(
            w3_w + (long long)l * Dc * DFFc, pwb, Dc, DFFc, KP_FF);
        launch_gemm<EP_ADD>(pa3, pwb, px, NTc, Dc, KP_FF, 0, 0, 1, nullptr);
    }

    // ---- final norm + logits ----
    norm_split_kernel<<<NTc, 256>>>(px, fn_w, KP_D);

    wcvt_kernel<<<(unsigned)(((long long)Vc * KP_D + 255) / 256), 256>>>(
        emb, pwb, Vc, Dc, KP_D);
    launch_gemm<EP_NONE>(pa3, pwb, logits, NTc, Vc, KP_D, 0, 0, 1, nullptr);
}